// round 10
// baseline (speedup 1.0000x reference)
#include <cuda_runtime.h>
#include <math.h>

#define NQb 12
#define SDIM 4096
#define TPB 128

typedef unsigned long long u64;

// ---------- packed f32x2 helpers ----------
__device__ __forceinline__ u64 pk2(float lo, float hi) {
    u64 r; asm("mov.b64 %0,{%1,%2};" : "=l"(r) : "f"(lo), "f"(hi)); return r;
}
__device__ __forceinline__ void unpk2(u64 v, float& lo, float& hi) {
    asm("mov.b64 {%0,%1},%2;" : "=f"(lo), "=f"(hi) : "l"(v));
}
__device__ __forceinline__ u64 f2mul(u64 a, u64 b) {
    u64 d; asm("mul.rn.f32x2 %0,%1,%2;" : "=l"(d) : "l"(a), "l"(b)); return d;
}
__device__ __forceinline__ u64 f2fma(u64 a, u64 b, u64 c) {
    u64 d; asm("fma.rn.f32x2 %0,%1,%2,%3;" : "=l"(d) : "l"(a), "l"(b), "l"(c)); return d;
}
__device__ __forceinline__ u64 cswap(u64 v) {
    float x, y; unpk2(v, x, y); return pk2(y, x);
}
__device__ __forceinline__ u64 cmulp(u64 a, float br, float bi) {   // a*(br+i bi)
    return f2fma(pk2(-bi, bi), cswap(a), f2mul(pk2(br, br), a));
}
__device__ __forceinline__ u64 cmul2(u64 a, u64 b) {
    float br, bi; unpk2(b, br, bi); return cmulp(a, br, bi);
}

// split-barrier macros: named barrier, 128 arrivals + 128 sync-entries = 256
#define BAR_ARRIVE(id) asm volatile("bar.arrive %0, 256;" :: "n"(id) : "memory")
#define BAR_SYNCW(id)  asm volatile("bar.sync %0, 256;"   :: "n"(id) : "memory")

// swizzle alpha: conflict-free for pass-A (128-bit), pass-B load and tau-store (64-bit)
__device__ __forceinline__ int alpha(int k) {
    const int t = k >> 5;
    return k ^ ((t & 7) << 1) ^ (((t >> 5) & 1) << 3) ^ (((t >> 6) & 1) << 4);
}

// CNOT-chain permutation (verified): state_after[k] = state_before[sigma(k)]
__device__ __forceinline__ int sigma12(int x) {
    x ^= (x & 1) << 11;
#pragma unroll
    for (int p = 1; p <= 11; ++p) x ^= ((x >> p) & 1) << (p - 1);
    return x;
}
// tau = sigma^{-1}
__device__ __forceinline__ int tau12(int x) {
#pragma unroll
    for (int p = 11; p >= 1; --p) x ^= ((x >> p) & 1) << (p - 1);
    x ^= (x & 1) << 11;
    return x;
}

// 5 RY rotations via lifting (3 FMA per pair): reg bit bb <-> qubit (QHI-bb).
template <int QHI>
__device__ __forceinline__ void ry5_lift(u64 a[32], const float* __restrict__ tpL,
                                         const float* __restrict__ sryL) {
#pragma unroll
    for (int bb = 0; bb < 5; ++bb) {
        const float p = tpL[QHI - bb], q = sryL[QHI - bb];
        const u64 pp = pk2(p, p), qq = pk2(q, q);
        const int m = 1 << bb;
#pragma unroll
        for (int j0 = 0; j0 < 32; ++j0) {
            if (j0 & m) continue;        // compile-time pruned
            const int j1 = j0 | m;
            a[j0] = f2fma(pp, a[j1], a[j0]);
            a[j1] = f2fma(qq, a[j0], a[j1]);
            a[j0] = f2fma(pp, a[j1], a[j0]);
        }
    }
}

// shuffle-RY (partner across lanes)
__device__ __forceinline__ void ry_shfl(u64 a[32], float c, float s, int lane, int M) {
    const u64 cc = pk2(c, c);
    const float g = (lane & M) ? s : -s;
    const u64 sg = pk2(g, g);
#pragma unroll
    for (int j = 0; j < 32; ++j) {
        const u64 p = __shfl_xor_sync(0xffffffffu, a[j], M);
        a[j] = f2fma(sg, p, f2mul(cc, a[j]));
    }
}

__global__ void __launch_bounds__(TPB, 4)
qsim_kernel(const float* __restrict__ xin, const float* __restrict__ params,
            const float* __restrict__ lin_w, const float* __restrict__ lin_b,
            float* __restrict__ out) {
    __shared__ u64 samp[SDIM];             // packed (re,im), slot alpha(k) (tau-folded post-CNOT)
    __shared__ u64 TLs[64], THs[64];       // layer-0 product tables
    __shared__ float2 sv[NQb][2];
    __shared__ float cry[60], sry[60];     // RY cos/sin (cry only for shfl qubits)
    __shared__ float tP[60];               // RY lifting coefficient -tan(th/2)
    __shared__ float tz[48];               // RZ angles, layers 1..4
    __shared__ float zoffB[4][32];         // RZ phase offsets for pass-B reg bits (qubits 6..2)
    __shared__ float Tsum[4];
    __shared__ float red4[4];

    const int t = threadIdx.x;
    const int blk = blockIdx.x;
    const int lane = t & 31;

    // ---------- setup ----------
    if (t < NQb) {
        const float h = tanhf(xin[blk * NQb + t]) * 1.5707963267948966f;
        const float ce = cosf(h), se = sinf(h);
        const float th = 0.5f * params[t];
        const float ct = cosf(th), st = sinf(th);
        const float a = ct * ce - st * se, b = st * ce + ct * se;
        const float t0 = params[NQb + t];
        const float c0 = cosf(0.5f * t0), s0 = sinf(0.5f * t0);
        sv[t][0] = make_float2(a * c0, -a * s0);
        sv[t][1] = make_float2(b * c0,  b * s0);
    }
    if (t < 60) {
        const int L = t / NQb, q = t - L * NQb;
        const float th = 0.5f * params[(L + 1) * 24 + q];
        cry[t] = cosf(th); sry[t] = sinf(th);
        tP[t] = -tanf(0.5f * th);          // lifting coefficient
    }
    if (t < 48) {
        const int L = t / NQb, q = t - L * NQb;
        tz[t] = params[(L + 1) * 24 + NQb + q];
    }
    __syncthreads();

    // product tables: TL over qubits 11..6 (k bits 0-5), TH over qubits 5..0 (k bits 6-11)
    {
        const int n = t & 63;
        const int qb = (t < 64) ? 11 : 5;
        float2 a = sv[qb][n & 1];
#pragma unroll
        for (int p = 1; p < 6; ++p) {
            const float2 w = sv[qb - p][(n >> p) & 1];
            a = make_float2(a.x * w.x - a.y * w.y, a.x * w.y + a.y * w.x);
        }
        if (t < 64) TLs[n] = pk2(a.x, a.y); else THs[n] = pk2(a.x, a.y);
    }
    {   // zoffB[L][j]: pass-B reg bit bb (k bit 5+bb) <-> qubit (6-bb)
        const int L = t >> 5, j = t & 31;
        const float* tzL = tz + L * NQb;
        float zo = 0.f;
#pragma unroll
        for (int bb = 0; bb < 5; ++bb)
            if ((j >> bb) & 1) zo += tzL[6 - bb];
        zoffB[L][j] = zo;
    }
    if (t < 4) {
        float s = 0.f;
#pragma unroll
        for (int q = 0; q < NQb; ++q) s += tz[t * NQb + q];
        Tsum[t] = s;
    }
    __syncthreads();

    // ---------- per-thread invariants ----------
    const int A_t = alpha(t << 5);
    const int w2 = (t >> 5) & 3, h2 = (t >> 3) & 3;
    const int kBt = (t & 7) | (w2 << 3) | (h2 << 10);
    const int B_t = alpha(kBt);
    const int PT_t = alpha(tau12(kBt));    // tau-fold store, t-part
    const int TAU_t = tau12(kBt);          // measurement fold

    float phb[4];
#pragma unroll
    for (int L = 0; L < 4; ++L) {
        const float* tzL = tz + L * NQb;
        float p = -0.5f * Tsum[L];
        if (t & 1)  p += tzL[11];
        if (t & 2)  p += tzL[10];
        if (t & 4)  p += tzL[9];
        if (t & 32) p += tzL[8];
        if (t & 64) p += tzL[7];
        if (t & 8)  p += tzL[1];
        if (t & 16) p += tzL[0];
        phb[L] = p;
    }

    // ---------- layer-1 pass-A input: layer 0 + CNOT folded ----------
    const int S_t = sigma12(t << 5);
    u64 amp[32];
#pragma unroll
    for (int j = 0; j < 32; ++j) {
        const int m = S_t ^ sigma12(j);
        amp[j] = cmul2(TLs[m & 63], THs[(m >> 6) & 63]);
    }

    float accm = 0.f;

#pragma unroll 1
    for (int L = 0; L < 5; ++L) {          // physical layers 1..5
        const float* tpL  = tP  + L * NQb;
        const float* sryL = sry + L * NQb;
        const float* cryL = cry + L * NQb;

        // pass A: qubits 11..7 on reg bits (own slots; CNOT pre-folded by tau-store)
        if (L) {
#pragma unroll
            for (int j = 0; j < 32; j += 2) {
                const ulonglong2 v = *reinterpret_cast<const ulonglong2*>(&samp[A_t ^ j]);
                amp[j] = v.x; amp[j + 1] = v.y;
            }
        }
        ry5_lift<11>(amp, tpL, sryL);
#pragma unroll
        for (int j = 0; j < 32; j += 2) {
            ulonglong2 v; v.x = amp[j]; v.y = amp[j + 1];
            *reinterpret_cast<ulonglong2*>(&samp[A_t ^ j]) = v;
        }

        if (L < 4) {
            // ---- BAR1 split: hide RZ phase-factor precompute (amp-independent) ----
            BAR_ARRIVE(2);
            const float* zoL = zoffB[L];
            float cpv[8], spv[8];
#pragma unroll
            for (int j = 0; j < 8; ++j)
                __sincosf(phb[L] + zoL[j], &spv[j], &cpv[j]);
            BAR_SYNCW(2);

            // pass B: qubits 6..2 on reg bits, qubits 1,0 on lane bits 3,4
#pragma unroll
            for (int j = 0; j < 32; ++j)
                amp[j] = samp[B_t ^ ((j << 5) ^ ((j & 7) << 1))];
            ry5_lift<6>(amp, tpL, sryL);

            // ---- BAR2 split: all pass-B loads consumed; hide shfl + RZ ----
            BAR_ARRIVE(1);
            ry_shfl(amp, cryL[1], sryL[1], lane, 8);
            ry_shfl(amp, cryL[0], sryL[0], lane, 16);
#pragma unroll
            for (int j = 0; j < 8; ++j)
                amp[j] = cmulp(amp[j], cpv[j], spv[j]);
#pragma unroll
            for (int j = 8; j < 32; ++j) {
                float sp, cp;
                __sincosf(phb[L] + zoL[j], &sp, &cp);
                amp[j] = cmulp(amp[j], cp, sp);
            }
            BAR_SYNCW(1);

            // CNOT fold: amp(kB) -> slot alpha(tau(kB))
#pragma unroll
            for (int j = 0; j < 32; ++j)
                samp[PT_t ^ alpha(tau12(j << 5))] = amp[j];
            __syncthreads();
        } else {
            // last layer: plain full barrier, then pass B + measurement (no store)
            __syncthreads();
#pragma unroll
            for (int j = 0; j < 32; ++j)
                amp[j] = samp[B_t ^ ((j << 5) ^ ((j & 7) << 1))];
            ry5_lift<6>(amp, tpL, sryL);
            ry_shfl(amp, cryL[1], sryL[1], lane, 8);
            ry_shfl(amp, cryL[0], sryL[0], lane, 16);

            // RZ is |.|^2-invariant; fold final CNOT into weights
            u64 accp = 0ull;
#pragma unroll
            for (int j = 0; j < 32; ++j) {
                const int tm = TAU_t ^ tau12(j << 5);
                const float w = (float)(NQb - 2 * __popc(tm));
                accp = f2fma(f2mul(amp[j], amp[j]), pk2(w, w), accp);
            }
            float wl, wh; unpk2(accp, wl, wh);
            accm = wl + wh;
        }
    }

    // ---------- reduction (4 warps) + head ----------
#pragma unroll
    for (int o = 16; o; o >>= 1) accm += __shfl_xor_sync(0xffffffffu, accm, o);
    if (lane == 0) red4[t >> 5] = accm;
    __syncthreads();
    if (t == 0) {
        const float m = red4[0] + red4[1] + red4[2] + red4[3];
        const float z = (m / (float)NQb) * lin_w[0] + lin_b[0];
        out[blk] = 1.f / (1.f + expf(-z));
    }
}

extern "C" void kernel_launch(void* const* d_in, const int* in_sizes, int n_in,
                              void* d_out, int out_size) {
    const float* x      = (const float*)d_in[0];
    const float* params = (const float*)d_in[1];
    const float* lw     = (const float*)d_in[2];
    const float* lb     = (const float*)d_in[3];
    const int Bn = in_sizes[0] / NQb;      // 512
    qsim_kernel<<<Bn, TPB>>>(x, params, lw, lb, (float*)d_out);
}

// round 11
// speedup vs baseline: 1.1309x; 1.1309x over previous
#include <cuda_runtime.h>
#include <math.h>

#define NQb 12
#define SDIM 4096
#define TPB 256

typedef unsigned long long u64;

// ---------- packed f32x2 helpers ----------
__device__ __forceinline__ u64 pk2(float lo, float hi) {
    u64 r; asm("mov.b64 %0,{%1,%2};" : "=l"(r) : "f"(lo), "f"(hi)); return r;
}
__device__ __forceinline__ void unpk2(u64 v, float& lo, float& hi) {
    asm("mov.b64 {%0,%1},%2;" : "=f"(lo), "=f"(hi) : "l"(v));
}
__device__ __forceinline__ u64 f2mul(u64 a, u64 b) {
    u64 d; asm("mul.rn.f32x2 %0,%1,%2;" : "=l"(d) : "l"(a), "l"(b)); return d;
}
__device__ __forceinline__ u64 f2fma(u64 a, u64 b, u64 c) {
    u64 d; asm("fma.rn.f32x2 %0,%1,%2,%3;" : "=l"(d) : "l"(a), "l"(b), "l"(c)); return d;
}
__device__ __forceinline__ u64 cswap(u64 v) {
    float x, y; unpk2(v, x, y); return pk2(y, x);
}
__device__ __forceinline__ u64 cmulp(u64 a, float br, float bi) {   // a*(br+i bi)
    return f2fma(pk2(-bi, bi), cswap(a), f2mul(pk2(br, br), a));
}
__device__ __forceinline__ u64 cmul2(u64 a, u64 b) {
    float br, bi; unpk2(b, br, bi); return cmulp(a, br, bi);
}

// swizzle beta: conflict-free per 16-lane phase for pass A/B/C and tau-store
__device__ __forceinline__ int beta_s(int k) { return k ^ ((k >> 4) & 15); }

// CNOT-chain permutation (verified): state_after[k] = state_before[sigma(k)]
__device__ __forceinline__ int sigma12(int x) {
    x ^= (x & 1) << 11;
#pragma unroll
    for (int p = 1; p <= 11; ++p) x ^= ((x >> p) & 1) << (p - 1);
    return x;
}
// tau = sigma^{-1}
__device__ __forceinline__ int tau12(int x) {
#pragma unroll
    for (int p = 11; p >= 1; --p) x ^= ((x >> p) & 1) << (p - 1);
    x ^= (x & 1) << 11;
    return x;
}

// 4 RY rotations via lifting (3 FMA per pair): reg bit bb <-> qubit (QHI-bb).
// x' = x + p*y ; y' = y + q*x' ; x'' = x' + p*y'   (p=-tan(th/2), q=sin th)
template <int QHI>
__device__ __forceinline__ void ry4_lift(u64 a[16], const float* __restrict__ tpL,
                                         const float* __restrict__ sryL) {
#pragma unroll
    for (int bb = 0; bb < 4; ++bb) {
        const float p = tpL[QHI - bb], q = sryL[QHI - bb];
        const u64 pp = pk2(p, p), qq = pk2(q, q);
        const int m = 1 << bb;
#pragma unroll
        for (int j0 = 0; j0 < 16; ++j0) {
            if (j0 & m) continue;        // compile-time pruned
            const int j1 = j0 | m;
            a[j0] = f2fma(pp, a[j1], a[j0]);
            a[j1] = f2fma(qq, a[j0], a[j1]);
            a[j0] = f2fma(pp, a[j1], a[j0]);
        }
    }
}

__global__ void __launch_bounds__(TPB, 4)
qsim_kernel(const float* __restrict__ xin, const float* __restrict__ params,
            const float* __restrict__ lin_w, const float* __restrict__ lin_b,
            float* __restrict__ out) {
    __shared__ u64 samp[SDIM];             // packed (re,im), slot beta(k) (tau-folded post-CNOT)
    __shared__ u64 TLs[64], THs[64];       // layer-0 product tables
    __shared__ float2 sv[NQb][2];
    __shared__ float sry[60];              // sin(th) (lifting q), layers 1..5
    __shared__ float tP[60];               // -tan(th/2) (lifting p)
    __shared__ float tz[48];               // RZ angles, layers 1..4
    __shared__ float zoffC[4][16];         // RZ offsets for pass-C reg bits (qubits 3..0)
    __shared__ float Tsum[4];
    __shared__ float red8[8];

    const int t = threadIdx.x;             // 8 bits
    const int blk = blockIdx.x;
    const int lane = t & 31;

    // ---------- setup ----------
    if (t < NQb) {
        const float h = tanhf(xin[blk * NQb + t]) * 1.5707963267948966f;
        const float ce = cosf(h), se = sinf(h);
        const float th = 0.5f * params[t];
        const float ct = cosf(th), st = sinf(th);
        const float a = ct * ce - st * se, b = st * ce + ct * se;
        const float t0 = params[NQb + t];
        const float c0 = cosf(0.5f * t0), s0 = sinf(0.5f * t0);
        sv[t][0] = make_float2(a * c0, -a * s0);
        sv[t][1] = make_float2(b * c0,  b * s0);
    }
    if (t < 60) {
        const int L = t / NQb, q = t - L * NQb;
        const float th = 0.5f * params[(L + 1) * 24 + q];
        sry[t] = sinf(th);
        tP[t] = -tanf(0.5f * th);
    }
    if (t < 48) {
        const int L = t / NQb, q = t - L * NQb;
        tz[t] = params[(L + 1) * 24 + NQb + q];
    }
    __syncthreads();

    // product tables: TL over qubits 11..6 (k bits 0-5), TH over qubits 5..0 (k bits 6-11)
    if (t < 128) {
        const int n = t & 63;
        const int qb = (t < 64) ? 11 : 5;
        float2 a = sv[qb][n & 1];
#pragma unroll
        for (int p = 1; p < 6; ++p) {
            const float2 w = sv[qb - p][(n >> p) & 1];
            a = make_float2(a.x * w.x - a.y * w.y, a.x * w.y + a.y * w.x);
        }
        if (t < 64) TLs[n] = pk2(a.x, a.y); else THs[n] = pk2(a.x, a.y);
    }
    if (t < 64) {   // zoffC[L][j]: pass-C reg bit bb (k bit 8+bb) <-> qubit (3-bb)
        const int L = t >> 4, j = t & 15;
        const float* tzL = tz + L * NQb;
        float zo = 0.f;
#pragma unroll
        for (int bb = 0; bb < 4; ++bb)
            if ((j >> bb) & 1) zo += tzL[3 - bb];
        zoffC[L][j] = zo;
    }
    if (t >= 128 && t < 132) {
        const int L = t - 128; float s = 0.f;
#pragma unroll
        for (int q = 0; q < NQb; ++q) s += tz[L * NQb + q];
        Tsum[L] = s;
    }
    __syncthreads();

    // ---------- per-thread invariants ----------
    const int Abase = (t << 4) ^ (t & 15);             // beta((t<<4)|j) = Abase ^ j
    const int Bbase = (t & 15) | ((t >> 4) << 8);      // beta(kB) = Bbase ^ (j<<4) ^ j
    const int Cbase = t ^ ((t >> 4) & 15);             // beta(kC) = Cbase ^ (j<<8)
    const int PT_t  = beta_s(tau12(t));                // tau-store, t-part
    const int TAU_t = tau12(t);                        // measurement fold

    // ---------- layer-1 pass-A input: layer 0 + CNOT folded, kA=(t<<4)|j ----------
    const int S_t = sigma12(t << 4);
    u64 amp[16];
#pragma unroll
    for (int j = 0; j < 16; ++j) {
        const int m = S_t ^ sigma12(j);
        amp[j] = cmul2(TLs[m & 63], THs[(m >> 6) & 63]);
    }

    float accm = 0.f;

#pragma unroll 1
    for (int L = 0; L < 5; ++L) {          // physical layers 1..5
        const float* tpL  = tP  + L * NQb;
        const float* sryL = sry + L * NQb;

        // pass A: k bits 0-3 on regs <-> qubits 11..8 (in-place per-thread)
        if (L) {
#pragma unroll
            for (int j = 0; j < 16; ++j) amp[j] = samp[Abase ^ j];
        }
        ry4_lift<11>(amp, tpL, sryL);
#pragma unroll
        for (int j = 0; j < 16; ++j) samp[Abase ^ j] = amp[j];
        __syncthreads();

        // pass B: k bits 4-7 on regs <-> qubits 7..4 (in-place per-thread)
#pragma unroll
        for (int j = 0; j < 16; ++j) amp[j] = samp[Bbase ^ ((j << 4) ^ j)];
        ry4_lift<7>(amp, tpL, sryL);
#pragma unroll
        for (int j = 0; j < 16; ++j) samp[Bbase ^ ((j << 4) ^ j)] = amp[j];
        __syncthreads();

        // pass C: k bits 8-11 on regs <-> qubits 3..0
#pragma unroll
        for (int j = 0; j < 16; ++j) amp[j] = samp[Cbase ^ (j << 8)];
        ry4_lift<3>(amp, tpL, sryL);

        if (L < 4) {
            // fused RZ: phase(kC) = phb(t) + zoffC[L][j];  t bit b <-> qubit (11-b)
            const float* tzL = tz + L * NQb;
            float phb = -0.5f * Tsum[L];
            if (t & 1)   phb += tzL[11];
            if (t & 2)   phb += tzL[10];
            if (t & 4)   phb += tzL[9];
            if (t & 8)   phb += tzL[8];
            if (t & 16)  phb += tzL[7];
            if (t & 32)  phb += tzL[6];
            if (t & 64)  phb += tzL[5];
            if (t & 128) phb += tzL[4];
            const float* zoL = zoffC[L];
#pragma unroll
            for (int j = 0; j < 16; ++j) {
                float sp, cp;
                __sincosf(phb + zoL[j], &sp, &cp);
                amp[j] = cmulp(amp[j], cp, sp);
            }
            __syncthreads();   // all pass-C loads consumed before permuted overwrite
            // CNOT fold: amp(kC) -> slot beta(tau(kC))
#pragma unroll
            for (int j = 0; j < 16; ++j)
                samp[PT_t ^ beta_s(tau12(j << 8))] = amp[j];
            __syncthreads();
        } else {
            // last layer: RZ is |.|^2-invariant; fold final CNOT into weights
            u64 accp = 0ull;
#pragma unroll
            for (int j = 0; j < 16; ++j) {
                const int tm = TAU_t ^ tau12(j << 8);
                const float w = (float)(NQb - 2 * __popc(tm));
                accp = f2fma(f2mul(amp[j], amp[j]), pk2(w, w), accp);
            }
            float wl, wh; unpk2(accp, wl, wh);
            accm = wl + wh;
        }
    }

    // ---------- reduction (8 warps) + head ----------
#pragma unroll
    for (int o = 16; o; o >>= 1) accm += __shfl_xor_sync(0xffffffffu, accm, o);
    if (lane == 0) red8[t >> 5] = accm;
    __syncthreads();
    if (t == 0) {
        float m = 0.f;
#pragma unroll
        for (int w = 0; w < 8; ++w) m += red8[w];
        const float z = (m / (float)NQb) * lin_w[0] + lin_b[0];
        out[blk] = 1.f / (1.f + expf(-z));
    }
}

extern "C" void kernel_launch(void* const* d_in, const int* in_sizes, int n_in,
                              void* d_out, int out_size) {
    const float* x      = (const float*)d_in[0];
    const float* params = (const float*)d_in[1];
    const float* lw     = (const float*)d_in[2];
    const float* lb     = (const float*)d_in[3];
    const int Bn = in_sizes[0] / NQb;      // 512
    qsim_kernel<<<Bn, TPB>>>(x, params, lw, lb, (float*)d_out);
}